// round 9
// baseline (speedup 1.0000x reference)
#include <cuda_runtime.h>
#include <cuda_fp16.h>
#include <math.h>
#include <stdint.h>

// ---------------------------------------------------------------------------
// CortexBlock on GB300 (compute_103 pipeline => mma.sync HMMA path)
// B=4, T=2048, D=1024, H=16, Dh=64, R=16
// GEMMs: single-pass fp16 (fp32 accumulate), 64x64 warp tiles, CTA 128x256.
// Scan: warp-per-head, shuffle-only (no barriers, no smem).
// ---------------------------------------------------------------------------

#define D_MODEL 1024
#define N_HEADS 16
#define D_HEAD  64
#define RANK    16
#define DECAY   0.95f
#define ALPHA_MAX 0.05f
#define BETA    0.01f

#define BB 4
#define TT 2048
#define BT (BB*TT)   // 8192

// ---------------- scratch (static device globals; no allocs allowed) -------
__device__ __align__(256) __half g_xh[BT * D_MODEL];
__device__ __align__(256) __half g_w[4 * D_MODEL * D_MODEL];   // Wq,Wk,Wv,Wo fp16
__device__ __align__(256) __half g_yh[BT * D_MODEL];
__device__ __align__(256) float g_q[BT * D_MODEL];
__device__ __align__(256) float g_k[BT * D_MODEL];
__device__ __align__(256) float g_v[BT * D_MODEL];
__device__ __align__(256) float g_alpha[BT * N_HEADS];

// ---------------- small asm helpers ----------------------------------------
__device__ __forceinline__ uint32_t smem_u32(const void* p) {
    uint32_t a;
    asm("{ .reg .u64 t; cvta.to.shared.u64 t, %1; cvt.u32.u64 %0, t; }"
        : "=r"(a) : "l"(p));
    return a;
}
__device__ __forceinline__ void cp_async16(uint32_t daddr, const void* gaddr) {
    asm volatile("cp.async.cg.shared.global [%0], [%1], 16;"
                 :: "r"(daddr), "l"(gaddr) : "memory");
}
#define CP_COMMIT()  asm volatile("cp.async.commit_group;" ::: "memory")
#define CP_WAIT(n)   asm volatile("cp.async.wait_group %0;" :: "n"(n) : "memory")

__device__ __forceinline__ void ldsm_x4(uint32_t (&r)[4], uint32_t addr) {
    asm volatile("ldmatrix.sync.aligned.m8n8.x4.shared.b16 {%0,%1,%2,%3}, [%4];"
                 : "=r"(r[0]), "=r"(r[1]), "=r"(r[2]), "=r"(r[3]) : "r"(addr));
}
__device__ __forceinline__ void mma_16816_f16(float (&d)[4], const uint32_t (&a)[4],
                                              uint32_t b0, uint32_t b1) {
    asm volatile(
        "mma.sync.aligned.m16n8k16.row.col.f32.f16.f16.f32 "
        "{%0,%1,%2,%3}, {%4,%5,%6,%7}, {%8,%9}, {%0,%1,%2,%3};"
        : "+f"(d[0]), "+f"(d[1]), "+f"(d[2]), "+f"(d[3])
        : "r"(a[0]), "r"(a[1]), "r"(a[2]), "r"(a[3]), "r"(b0), "r"(b1));
}

// ---------------------------------------------------------------------------
// fp16 single-pass GEMM: C[M,N](fp32) = A[M,K] * W[N,K]^T
// CTA tile 128(M) x 256(N), K-chunk 64. 8 warps = 2(m) x 4(n) of 64x64 tiles.
// 3-stage cp.async pipeline, 1 barrier per chunk. smem row stride 72 halves.
// ---------------------------------------------------------------------------
#define GM 128
#define GN 256
#define GKC 64
#define AST 72
#define A_BYTES (GM * AST * 2)            // 18432
#define B_BYTES (GN * AST * 2)            // 36864
#define STAGE_BYTES (A_BYTES + B_BYTES)   // 55296
#define NSTAGE 3
#define GEMM_SMEM_BYTES (NSTAGE * STAGE_BYTES)   // 165888

__global__ __launch_bounds__(256, 1) void gemm_f16(
    const __half* __restrict__ A, const __half* __restrict__ Wbase,
    float* __restrict__ C0, float* __restrict__ C1, float* __restrict__ C2,
    int M, int N, int K)
{
    extern __shared__ __half smem[];

    const int tid  = threadIdx.x;
    const int wid  = tid >> 5;
    const int lane = tid & 31;
    const int rowBase = blockIdx.y * GM;
    const int colBase = blockIdx.x * GN;
    const int z = blockIdx.z;

    const __half* Bw = Wbase + (size_t)z * D_MODEL * D_MODEL;
    float* C = (z == 0) ? C0 : (z == 1) ? C1 : C2;

    const int wm = (wid & 1) * 64;        // warp m offset
    const int wn = (wid >> 1) * 64;       // warp n offset

    const uint32_t smBase = smem_u32(smem);

    float acc[4][8][4];
#pragma unroll
    for (int i = 0; i < 4; i++)
#pragma unroll
        for (int j = 0; j < 8; j++)
#pragma unroll
            for (int c = 0; c < 4; c++) acc[i][j][c] = 0.0f;

    const int aRow = lane & 15;
    const int aKo  = (lane >> 4) * 8;
    const int bNo  = ((lane >> 4) << 3) + (lane & 7);
    const int bKo  = ((lane >> 3) & 1) * 8;

    const int NCH = K / GKC;              // 16

    auto issue = [&](int ci) {
        const int k0 = ci * GKC;
        const uint32_t stage = smBase + (uint32_t)(ci % NSTAGE) * STAGE_BYTES;
        // A: 128 rows x 8 segs = 1024 transfers (4 per thread)
#pragma unroll
        for (int i = 0; i < 4; i++) {
            int L = tid + (i << 8);
            int row = L >> 3;
            int seg = L & 7;
            cp_async16(stage + (uint32_t)row * (AST * 2) + seg * 16,
                       A + (size_t)(rowBase + row) * K + k0 + seg * 8);
        }
        // B: 256 rows x 8 segs = 2048 transfers (8 per thread)
#pragma unroll
        for (int i = 0; i < 8; i++) {
            int L = tid + (i << 8);
            int row = L >> 3;
            int seg = L & 7;
            cp_async16(stage + A_BYTES + (uint32_t)row * (AST * 2) + seg * 16,
                       Bw + (size_t)(colBase + row) * K + k0 + seg * 8);
        }
        CP_COMMIT();
    };

    issue(0);
    issue(1);

    for (int ci = 0; ci < NCH; ci++) {
        CP_WAIT(1);                       // chunk ci complete
        __syncthreads();
        if (ci + 2 < NCH) issue(ci + 2);
        else CP_COMMIT();                 // keep group counting correct

        const uint32_t stage  = smBase + (uint32_t)(ci % NSTAGE) * STAGE_BYTES;
        const uint32_t bBase0 = stage + A_BYTES;

#pragma unroll
        for (int ks = 0; ks < 4; ks++) {
            uint32_t Ar[4][4];
#pragma unroll
            for (int mi = 0; mi < 4; mi++) {
                uint32_t addr = stage + (uint32_t)(wm + mi * 16 + aRow) * (AST * 2)
                              + (uint32_t)(ks * 16 + aKo) * 2;
                ldsm_x4(Ar[mi], addr);
            }
            uint32_t Br[4][4];
#pragma unroll
            for (int ni = 0; ni < 4; ni++) {
                uint32_t addr = bBase0 + (uint32_t)(wn + ni * 16 + bNo) * (AST * 2)
                              + (uint32_t)(ks * 16 + bKo) * 2;
                ldsm_x4(Br[ni], addr);
            }
#pragma unroll
            for (int mi = 0; mi < 4; mi++)
#pragma unroll
                for (int j = 0; j < 8; j++)
                    mma_16816_f16(acc[mi][j], Ar[mi],
                                  Br[j >> 1][(j & 1) * 2], Br[j >> 1][(j & 1) * 2 + 1]);
        }
    }

    // epilogue
#pragma unroll
    for (int mi = 0; mi < 4; mi++) {
        const int row0 = rowBase + wm + mi * 16 + (lane >> 2);
#pragma unroll
        for (int j = 0; j < 8; j++) {
            const int col = colBase + wn + j * 8 + (lane & 3) * 2;
            *reinterpret_cast<float2*>(C + (size_t)row0 * N + col) =
                make_float2(acc[mi][j][0], acc[mi][j][1]);
            *reinterpret_cast<float2*>(C + (size_t)(row0 + 8) * N + col) =
                make_float2(acc[mi][j][2], acc[mi][j][3]);
        }
    }
}

// ---------------------------------------------------------------------------
// Fused x->fp16 convert + alpha. Block = 16 rows, 512 threads (16 heads).
// ---------------------------------------------------------------------------
__global__ __launch_bounds__(512) void cvtx_alpha_kernel(
    const float* __restrict__ x, const float* __restrict__ Wa,
    const float* __restrict__ ba, const float* __restrict__ m_gate,
    const float* __restrict__ ascale,
    __half* __restrict__ xh, float* __restrict__ alpha)
{
    extern __shared__ float xs[];        // [16][1024]
    const int tid  = threadIdx.x;
    const int warp = tid >> 5;           // head
    const int lane = tid & 31;
    const int rowBase = blockIdx.x * 16;

    const float4* xg = reinterpret_cast<const float4*>(x + (size_t)rowBase * D_MODEL);
#pragma unroll
    for (int it = 0; it < 8; it++) {
        int i = tid + it * 512;
        float4 v = xg[i];
        reinterpret_cast<float4*>(xs)[i] = v;
        __half2* ph = reinterpret_cast<__half2*>(xh + (size_t)rowBase * D_MODEL + i * 4);
        ph[0] = __half2(__float2half_rn(v.x), __float2half_rn(v.y));
        ph[1] = __half2(__float2half_rn(v.z), __float2half_rn(v.w));
    }
    __syncthreads();

    float wa[32];
#pragma unroll
    for (int i = 0; i < 32; i++)
        wa[i] = Wa[(size_t)warp * D_MODEL + i * 32 + lane];
    const float bw = ba[warp];

#pragma unroll 4
    for (int row = 0; row < 16; row++) {
        const float* xr = xs + row * D_MODEL;
        float s = 0.0f;
#pragma unroll
        for (int i = 0; i < 32; i++)
            s = fmaf(wa[i], xr[i * 32 + lane], s);
#pragma unroll
        for (int off = 16; off; off >>= 1)
            s += __shfl_xor_sync(0xFFFFFFFFu, s, off);
        if (lane == 0) {
            const int r = rowBase + row;
            float sg = __fdividef(1.0f, 1.0f + __expf(-(s + bw)));
            float a = sg * m_gate[r] * ascale[(size_t)r * N_HEADS + warp];
            alpha[(size_t)r * N_HEADS + warp] = fminf(a, ALPHA_MAX);
        }
    }
}

// ---------------------------------------------------------------------------
// Round all 4 weight matrices to fp16 in one launch. DW = 1<<20 elems each.
// ---------------------------------------------------------------------------
__global__ __launch_bounds__(256) void cvt4_kernel(
    const float* __restrict__ W0, const float* __restrict__ W1,
    const float* __restrict__ W2, const float* __restrict__ W3,
    __half* __restrict__ out)
{
    const int i = blockIdx.x * 256 + threadIdx.x;       // 0 .. 4M-1
    const int sel = i >> 20;
    const int off = i & ((1 << 20) - 1);
    const float* src = (sel == 0) ? W0 : (sel == 1) ? W1 : (sel == 2) ? W2 : W3;
    out[i] = __float2half_rn(src[off]);
}

// ---------------------------------------------------------------------------
// Sequential fast-weight scan: ONE WARP per (b,h); lane owns d=lane, d=lane+32.
// Shuffle-only reduction (no barriers, no smem). y(t-1) finalized inside step
// t so the score butterfly never sits on the state-recurrence critical path.
// ---------------------------------------------------------------------------
__global__ __launch_bounds__(32) void scan_kernel(
    const float* __restrict__ q, const float* __restrict__ k,
    const float* __restrict__ v, const float* __restrict__ alpha,
    __half* __restrict__ yh, int T)
{
    const int bh = blockIdx.x;
    const int b = bh / N_HEADS;
    const int h = bh % N_HEADS;
    const int lane = threadIdx.x;        // 0..31; owns d0=lane, d1=lane+32

    float U0[RANK], U1[RANK], V0[RANK], V1[RANK];
#pragma unroll
    for (int r = 0; r < RANK; r++) { U0[r] = U1[r] = V0[r] = V1[r] = 0.0f; }

    // after the 4-level compaction, lane L holds r = bitrev4(L & 15);
    // so ku[r] lives in lane bitrev4(r) (bitrev4 is an involution).
    static const int BREV[16] = {0, 8, 4, 12, 2, 10, 6, 14,
                                 1, 9, 5, 13, 3, 11, 7, 15};

    const size_t strideT = (size_t)N_HEADS * D_HEAD;   // 1024
    size_t idx = ((size_t)b * T * N_HEADS + h) * D_HEAD + lane;
    const size_t abase = (size_t)b * T * N_HEADS + h;

    float q0 = q[idx],      k0 = k[idx],      v0 = v[idx];
    float q1 = q[idx + 32], k1 = k[idx + 32], v1 = v[idx + 32];
    float a  = alpha[abase];

    float sp0 = 0.f, sp1 = 0.f;          // step t-1 scores (all lanes)
    float v0p = 0.f, v1p = 0.f, kf0p = 0.f, kf1p = 0.f;
    size_t idxprev = idx;

    for (int t = 0; t < T; t++) {
        const size_t nidx = idx + strideT;
        float nq0 = 0.f, nk0 = 0.f, nv0 = 0.f;
        float nq1 = 0.f, nk1 = 0.f, nv1 = 0.f, na = 0.f;
        if (t + 1 < T) {
            nq0 = q[nidx]; nk0 = k[nidx]; nv0 = v[nidx];
            nq1 = q[nidx + 32]; nk1 = k[nidx + 32]; nv1 = v[nidx + 32];
            na  = alpha[abase + (size_t)(t + 1) * N_HEADS];
        }

        // p partials against pre-decay state (decay folded into ktd)
        const float ktd0 = k0 * DECAY;
        const float ktd1 = k1 * DECAY;
        float p[RANK];
#pragma unroll
        for (int r = 0; r < RANK; r++)
            p[r] = fmaf(ktd1, U1[r], ktd0 * U0[r]);

        // 4-level reduce-scatter within 16-lane groups + xor16 combine
#pragma unroll
        for (int s = 1, cnt = 8; s <= 8; s <<= 1, cnt >>= 1) {
            const bool hi = (lane & s) != 0;
#pragma unroll
            for (int i = 0; i < cnt; i++) {
                float lo_v = p[i], hi_v = p[i + cnt];
                float send = hi ? lo_v : hi_v;
                float recv = __shfl_xor_sync(0xFFFFFFFFu, send, s);
                p[i] = (hi ? hi_v : lo_v) + recv;
            }
        }
        float vr = p[0] + __shfl_xor_sync(0xFFFFFFFFu, p[0], 16);

        // decay state while the shuffle tree drains
#pragma unroll
        for (int r = 0; r < RANK; r++) {
            U0[r] *= DECAY; U1[r] *= DECAY;
            V0[r] *= DECAY; V1[r] *= DECAY;
        }

        // broadcast: ku[r] from lane BREV[r] (16 independent shfls)
        float ku[RANK];
#pragma unroll
        for (int r = 0; r < RANK; r++)
            ku[r] = __shfl_sync(0xFFFFFFFFu, vr, BREV[r]);

        const float ak0 = a * k0, ak1 = a * k1;
        const float av0 = a * v0, av1 = a * v1;
        float kf0a = 0.f, kf0b = 0.f, kf1a = 0.f, kf1b = 0.f;
#pragma unroll
        for (int r = 0; r < RANK; r++) {
            float u0 = fmaf(ak0, ku[r], U0[r]);
            float u1 = fmaf(ak1, ku[r], U1[r]);
            float w0 = fmaf(av0, ku[r], V0[r]);
            float w1 = fmaf(av1, ku[r], V1[r]);
            u0 -= BETA * fminf(fmaxf(u0, -1.0f), 1.0f);
            u1 -= BETA * fminf(fmaxf(u1, -1.0f), 1.0f);
            w0 -= BETA * fminf(fmaxf(w0, -1.0f), 1.0f);
            w1 -= BETA * fminf(fmaxf(w1, -1.0f), 1.0f);
            U0[r] = u0; U1[r] = u1; V0[r] = w0; V1[r] = w1;
            if (r & 1) { kf0b = fmaf(u0, w0, kf0b); kf1b = fmaf(u1, w1, kf1b); }
            else       { kf0a = fmaf(u0, w0, kf0a); kf1a = fmaf(u1, w1, kf1a); }
        }
        const float kf0 = kf0a + kf0b;
        const float kf1 = kf1a + kf1b;

        // finalize y(t-1): its score butterfly completed long ago
        if (t > 0) {
            const float m1 = __fdividef(1.0f, 1.0f + __expf(sp0 - sp1));
            const float m0 = 1.0f - m1;
            yh[idxprev]      = __float2half_rn(m0 * v0p + m1 * kf0p);
            yh[idxprev + 32] = __float2half_rn(m0 * v1p + m1 * kf1p);
        }

        // this step's scores: warp butterfly (off the state chain)
        float s0 = fmaf(q1 * 0.125f, k1,  q0 * 0.125f * k0);
        float s1 = fmaf(q1 * 0.125f, kf1, q0 * 0.125f * kf0);
#pragma unroll
        for (int off = 16; off; off >>= 1) {
            s0 += __shfl_xor_sync(0xFFFFFFFFu, s0, off);
            s1 += __shfl_xor_sync(0xFFFFFFFFu, s1, off);
        }
        sp0 = s0; sp1 = s1;
        v0p = v0; v1p = v1; kf0p = kf0; kf1p = kf1; idxprev = idx;

        q0 = nq0; k0 = nk0; v0 = nv0;
        q1 = nq1; k1 = nk1; v1 = nv1;
        a = na;
        idx = nidx;
    }

    // tail: store y(T-1)
    {
        const float m1 = __fdividef(1.0f, 1.0f + __expf(sp0 - sp1));
        const float m0 = 1.0f - m1;
        yh[idxprev]      = __float2half_rn(m0 * v0p + m1 * kf0p);
        yh[idxprev + 32] = __float2half_rn(m0 * v1p + m1 * kf1p);
    }
}

// ---------------------------------------------------------------------------
// Launch
// ---------------------------------------------------------------------------
extern "C" void kernel_launch(void* const* d_in, const int* in_sizes, int n_in,
                              void* d_out, int out_size)
{
    const float* x      = (const float*)d_in[0];
    const float* m_gate = (const float*)d_in[1];
    const float* ascale = (const float*)d_in[2];
    const float* Wq     = (const float*)d_in[3];
    const float* Wk     = (const float*)d_in[4];
    const float* Wv     = (const float*)d_in[5];
    const float* Wo     = (const float*)d_in[6];
    const float* Wa     = (const float*)d_in[7];
    const float* ba     = (const float*)d_in[8];
    // d_in[9] = mix_logit: cancels in the 2-way softmax; unused.
    float* out = (float*)d_out;

    const int M = in_sizes[1] > 0 ? in_sizes[1] : BT;  // B*T
    const int T = M / BB;

    __half *xh, *wf, *yh;
    float *dq, *dk, *dv, *da;
    cudaGetSymbolAddress((void**)&xh, g_xh);
    cudaGetSymbolAddress((void**)&wf, g_w);
    cudaGetSymbolAddress((void**)&yh, g_yh);
    cudaGetSymbolAddress((void**)&dq, g_q);
    cudaGetSymbolAddress((void**)&dk, g_k);
    cudaGetSymbolAddress((void**)&dv, g_v);
    cudaGetSymbolAddress((void**)&da, g_alpha);

    const int DW = D_MODEL * D_MODEL;

    static bool attr_set = false;
    if (!attr_set) {
        cudaFuncSetAttribute(gemm_f16,
                             cudaFuncAttributeMaxDynamicSharedMemorySize, GEMM_SMEM_BYTES);
        cudaFuncSetAttribute(cvtx_alpha_kernel,
                             cudaFuncAttributeMaxDynamicSharedMemorySize, 16 * D_MODEL * 4);
        attr_set = true;
    }

    cvtx_alpha_kernel<<<M / 16, 512, 16 * D_MODEL * 4>>>(
        x, Wa, ba, m_gate, ascale, xh, da);

    cvt4_kernel<<<(4 * DW) / 256, 256>>>(Wq, Wk, Wv, Wo, wf);

    dim3 gqkv(D_MODEL / GN, M / GM, 3);   // (4, 64, 3)
    gemm_f16<<<gqkv, 256, GEMM_SMEM_BYTES>>>(xh, wf, dq, dk, dv, M, D_MODEL, D_MODEL);

    scan_kernel<<<BB * N_HEADS, 32>>>(dq, dk, dv, da, yh, T);

    dim3 go(D_MODEL / GN, M / GM, 1);     // (4, 64, 1)
    gemm_f16<<<go, 256, GEMM_SMEM_BYTES>>>(yh, wf + (size_t)3 * DW,
                                           out, out, out, M, D_MODEL, D_MODEL);
}